// round 5
// baseline (speedup 1.0000x reference)
#include <cuda_runtime.h>
#include <cuda_bf16.h>
#include <cstdint>
#include <math.h>

// ===================== constants =====================
static constexpr int DIMK = 128;

// smem layout (bytes), dynamic
static constexpr int TS      = 272;                // padded tile row stride (136 bf16)
static constexpr int TILE_B  = 128 * TS;           // 34816
static constexpr int SM_A    = 0;
static constexpr int SM_B0   = TILE_B;             // 34816
static constexpr int SM_B1   = 2 * TILE_B;         // 69632
static constexpr int SM_CA   = 3 * TILE_B;         // 104448, 4 slots x 1KB (float2[128])
static constexpr int SM_RED  = SM_CA + 4096;       // 108544, 128*2 floats
static constexpr int SMEM_TOTAL = SM_RED + 1024;   // 109568

// ===================== scratch (no cudaMalloc) =====================
__device__ __nv_bfloat16 g_Cb[2048 * DIMK];
__device__ float2 g_c2a[2048];          // (d_j = -s2*||c_j||^2 , alpha_j)
__device__ float  g_predsMM[2048];
__device__ float  g_partials[512];
__device__ float  g_preds_fallback[100352];

// ===================== PTX helpers =====================
__device__ __forceinline__ uint32_t smem_u32(const void* p) {
    uint32_t a;
    asm("{ .reg .u64 t; cvta.to.shared.u64 t, %1; cvt.u32.u64 %0, t; }" : "=r"(a) : "l"(p));
    return a;
}
__device__ __forceinline__ void cpa16(uint32_t dst, const void* src) {
    asm volatile("cp.async.cg.shared.global [%0], [%1], 16;" :: "r"(dst), "l"(src));
}
#define CP_COMMIT() asm volatile("cp.async.commit_group;" ::: "memory")
#define CP_WAIT0()  asm volatile("cp.async.wait_group 0;"  ::: "memory")

__device__ __forceinline__ void ldmx4(uint32_t* r, uint32_t addr) {
    asm volatile("ldmatrix.sync.aligned.m8n8.x4.shared.b16 {%0,%1,%2,%3}, [%4];"
                 : "=r"(r[0]), "=r"(r[1]), "=r"(r[2]), "=r"(r[3]) : "r"(addr));
}
__device__ __forceinline__ void mma16816(float* c, const uint32_t* a,
                                         uint32_t b0, uint32_t b1) {
    asm volatile("mma.sync.aligned.m16n8k16.row.col.f32.bf16.bf16.f32 "
                 "{%0,%1,%2,%3}, {%4,%5,%6,%7}, {%8,%9}, {%0,%1,%2,%3};"
                 : "+f"(c[0]), "+f"(c[1]), "+f"(c[2]), "+f"(c[3])
                 : "r"(a[0]), "r"(a[1]), "r"(a[2]), "r"(a[3]), "r"(b0), "r"(b1));
}
__device__ __forceinline__ float ex2f(float x) {
    float y; asm("ex2.approx.ftz.f32 %0, %1;" : "=f"(y) : "f"(x)); return y;
}

// ===================== centers conv: fp32 -> bf16, (d, alpha) =====================
__global__ void convC_kernel(const float* __restrict__ C,
                             __nv_bfloat16* __restrict__ Cb,
                             float2* __restrict__ c2a,
                             const float* __restrict__ alpha,
                             const float* __restrict__ sigma_p, int m)
{
    int row  = blockIdx.x * 8 + (threadIdx.x >> 5);
    int lane = threadIdx.x & 31;
    if (row >= m) return;
    float4 v = ((const float4*)(C + (size_t)row * DIMK))[lane];
    __nv_bfloat162 p0 = __floats2bfloat162_rn(v.x, v.y);
    __nv_bfloat162 p1 = __floats2bfloat162_rn(v.z, v.w);
    float r0 = __bfloat162float(p0.x), r1 = __bfloat162float(p0.y);
    float r2 = __bfloat162float(p1.x), r3 = __bfloat162float(p1.y);
    float s = r0*r0 + r1*r1 + r2*r2 + r3*r3;
    #pragma unroll
    for (int o = 16; o > 0; o >>= 1) s += __shfl_xor_sync(0xffffffffu, s, o);
    __nv_bfloat162* dst = (__nv_bfloat162*)(Cb + (size_t)row * DIMK) + lane * 2;
    dst[0] = p0; dst[1] = p1;
    if (lane == 0) {
        float sg = *sigma_p;
        float s2 = 1.44269504088896340736f / (2.f * sg * sg);
        c2a[row] = make_float2(-s2 * s, alpha[row]);
    }
}

// ===================== B-tile async loader (bf16 128x128) =====================
__device__ __forceinline__ void load_tile_async(uint32_t smBase,
                                                const __nv_bfloat16* __restrict__ src,
                                                int tid)
{
    #pragma unroll
    for (int it = 0; it < 8; ++it) {
        int i   = tid + it * 256;
        int row = i >> 4;
        int kb  = i & 15;
        cpa16(smBase + row * TS + kb * 16, (const char*)src + row * 256 + kb * 16);
    }
}

// ===================== fused RBF matvec (HMMA, pipelined epilogue) ==========
// Blocks [0, nBlocksX): rows of X -> preds ; rest: rows of centers -> predsMM
__global__ void __launch_bounds__(256)
rbf_hmma_kernel(const float* __restrict__ Xf, const float* __restrict__ Cf,
                const __nv_bfloat16* __restrict__ Cb,
                const float2* __restrict__ c2a,
                const float* __restrict__ sigma_p,
                float* __restrict__ preds, float* __restrict__ predsMM,
                int nRows, int nBlocksX, int mCols)
{
    extern __shared__ char smem[];
    const uint32_t sb = smem_u32(smem);
    const int tid   = threadIdx.x;
    const int lane  = tid & 31;
    const int wid   = tid >> 5;
    const int warpM = wid & 3;          // 4 warps over M (32 rows each)
    const int warpN = wid >> 2;         // 2 warps over N (64 cols each)
    const int g     = lane >> 2;
    const int tq    = lane & 3;

    const bool isX = ((int)blockIdx.x < nBlocksX);
    const float* Asrc  = isX ? Xf : Cf;
    const int   srcN   = isX ? nRows : mCols;
    float* outp        = isX ? preds : predsMM;
    const int rowBase  = (isX ? blockIdx.x : blockIdx.x - nBlocksX) * 128;

    const float sg     = *sigma_p;
    const float s2     = 1.44269504088896340736f / (2.f * sg * sg); // log2e/(2s^2)
    const float two_s2 = 2.f * s2;
    const float neg_s2 = -s2;

    // ---- prologue: start async C tile 0 + CA slot 0 ----
    load_tile_async(sb + SM_B0, Cb, tid);
    if (tid < 64) cpa16(sb + SM_CA + tid * 16, (const char*)c2a + tid * 16);
    CP_COMMIT();

    // ---- load A tile fp32 -> bf16 smem (coalesced) ----
    #pragma unroll
    for (int i = 0; i < 16; ++i) {
        int idx = tid + i * 256;            // 4096 float4 chunks
        int r = idx >> 5, c4 = idx & 31;
        int gr = rowBase + r; if (gr >= srcN) gr = srcN - 1;
        float4 v = ((const float4*)(Asrc + (size_t)gr * DIMK))[c4];
        __nv_bfloat162 p0 = __floats2bfloat162_rn(v.x, v.y);
        __nv_bfloat162 p1 = __floats2bfloat162_rn(v.z, v.w);
        uint2 w;
        w.x = *(const uint32_t*)&p0; w.y = *(const uint32_t*)&p1;
        *(uint2*)(smem + SM_A + r * TS + c4 * 8) = w;
    }
    CP_WAIT0();
    __syncthreads();

    // ---- row norms from ROUNDED bf16 (2 threads/row) ----
    {
        const int nr = tid >> 1, nh = tid & 1;
        float nrm = 0.f;
        #pragma unroll
        for (int j = 0; j < 8; ++j) {
            uint4 v = *(const uint4*)(smem + SM_A + nr * TS + nh * 128 + j * 16);
            const uint32_t* u = (const uint32_t*)&v;
            #pragma unroll
            for (int q = 0; q < 4; ++q) {
                float2 f = __bfloat1622float2(*(const __nv_bfloat162*)&u[q]);
                nrm = fmaf(f.x, f.x, nrm);
                nrm = fmaf(f.y, f.y, nrm);
            }
        }
        ((float*)(smem + SM_RED))[nr * 2 + nh] = nrm;
    }
    __syncthreads();

    // row constants: caR[mf*2+h8] = -s2 * ||row||^2
    float caR[4];
    {
        const float* red = (const float*)(smem + SM_RED);
        #pragma unroll
        for (int mf = 0; mf < 2; ++mf)
            #pragma unroll
            for (int h8 = 0; h8 < 2; ++h8) {
                int row = warpM * 32 + mf * 16 + g + h8 * 8;
                caR[mf*2 + h8] = neg_s2 * (red[row*2] + red[row*2 + 1]);
            }
    }

    // ---- persist all A fragments in registers (2 mf x 8 ks x 4 regs) ----
    const int ti = lane >> 3, rr = lane & 7;
    uint32_t aF[2][8][4];
    #pragma unroll
    for (int mf = 0; mf < 2; ++mf) {
        uint32_t base = sb + SM_A + (warpM*32 + mf*16 + (ti & 1)*8 + rr) * TS
                        + (ti >> 1) * 16;
        #pragma unroll
        for (int ks = 0; ks < 8; ++ks) ldmx4(aF[mf][ks], base + ks * 32);
    }

    // B ldmatrix offsets (4 groups of 16 cols)
    uint32_t bOff[4];
    #pragma unroll
    for (int p = 0; p < 4; ++p)
        bOff[p] = (warpN*64 + p*16 + (ti >> 1)*8 + rr) * TS + (ti & 1) * 16;

    float acc[2][2][4][4];          // [set][mf][nfl][e]
    float rowAcc[4] = {0.f, 0.f, 0.f, 0.f};
    const int nT = mCols >> 7;      // 16

    for (int t = 0; t < nT; ++t) {
        if (t + 1 < nT) {
            load_tile_async(sb + ((t & 1) ? SM_B0 : SM_B1),
                            Cb + (size_t)(t + 1) * 128 * DIMK, tid);
            if (tid < 64)
                cpa16(sb + SM_CA + ((t + 1) & 3) * 1024 + tid * 16,
                      (const char*)(c2a + (size_t)(t + 1) * 128) + tid * 16);
            CP_COMMIT();
        }
        const uint32_t bB = sb + ((t & 1) ? SM_B1 : SM_B0);

        #pragma unroll
        for (int h = 0; h < 2; ++h) {
            // zero current accumulator set
            #pragma unroll
            for (int mf = 0; mf < 2; ++mf)
                #pragma unroll
                for (int nfl = 0; nfl < 4; ++nfl)
                    #pragma unroll
                    for (int e = 0; e < 4; ++e) acc[h][mf][nfl][e] = 0.f;

            // epilogue source for the PREVIOUS half
            const bool doEpi = (h == 1) || (t > 0);
            const uint32_t epiCA = sb + SM_CA
                + (uint32_t)(((h == 0 ? t - 1 : t) & 3) * 1024)
                + (uint32_t)((warpN * 64 + (h == 0 ? 32 : 0)) * 8);

            #pragma unroll
            for (int ks = 0; ks < 8; ++ks) {
                uint32_t r0[4], r1[4];
                ldmx4(r0, bB + bOff[2*h]     + ks * 32);
                ldmx4(r1, bB + bOff[2*h + 1] + ks * 32);
                #pragma unroll
                for (int mf = 0; mf < 2; ++mf) {
                    mma16816(acc[h][mf][0], aF[mf][ks], r0[0], r0[1]);
                    mma16816(acc[h][mf][1], aF[mf][ks], r0[2], r0[3]);
                    mma16816(acc[h][mf][2], aF[mf][ks], r1[0], r1[1]);
                    mma16816(acc[h][mf][3], aF[mf][ks], r1[2], r1[3]);
                }
                // interleaved epilogue chunk of previous half (4 elems)
                if (doEpi) {
                    const int emf = ks & 1, enf = ks >> 1;
                    const float4 cc = *(const float4*)((const char*)smem
                        + (epiCA - sb) + (enf * 8 + tq * 2) * 8);
                    const float* a = acc[h ^ 1][emf][enf];
                    float e0 = fmaf(two_s2, a[0], caR[emf*2]     + cc.x);
                    float e1 = fmaf(two_s2, a[1], caR[emf*2]     + cc.z);
                    float e2 = fmaf(two_s2, a[2], caR[emf*2 + 1] + cc.x);
                    float e3 = fmaf(two_s2, a[3], caR[emf*2 + 1] + cc.z);
                    rowAcc[emf*2]     = fmaf(ex2f(e0), cc.y, rowAcc[emf*2]);
                    rowAcc[emf*2]     = fmaf(ex2f(e1), cc.w, rowAcc[emf*2]);
                    rowAcc[emf*2 + 1] = fmaf(ex2f(e2), cc.y, rowAcc[emf*2 + 1]);
                    rowAcc[emf*2 + 1] = fmaf(ex2f(e3), cc.w, rowAcc[emf*2 + 1]);
                }
            }
        }
        CP_WAIT0();
        __syncthreads();
    }

    // final epilogue: last tile's second half (set 1, slot (nT-1)&3, cols +32)
    {
        const uint32_t epiCA = (uint32_t)(SM_CA + ((nT - 1) & 3) * 1024
                                          + (warpN * 64 + 32) * 8);
        #pragma unroll
        for (int ks = 0; ks < 8; ++ks) {
            const int emf = ks & 1, enf = ks >> 1;
            const float4 cc = *(const float4*)(smem + epiCA + (enf*8 + tq*2) * 8);
            const float* a = acc[1][emf][enf];
            float e0 = fmaf(two_s2, a[0], caR[emf*2]     + cc.x);
            float e1 = fmaf(two_s2, a[1], caR[emf*2]     + cc.z);
            float e2 = fmaf(two_s2, a[2], caR[emf*2 + 1] + cc.x);
            float e3 = fmaf(two_s2, a[3], caR[emf*2 + 1] + cc.z);
            rowAcc[emf*2]     = fmaf(ex2f(e0), cc.y, rowAcc[emf*2]);
            rowAcc[emf*2]     = fmaf(ex2f(e1), cc.w, rowAcc[emf*2]);
            rowAcc[emf*2 + 1] = fmaf(ex2f(e2), cc.y, rowAcc[emf*2 + 1]);
            rowAcc[emf*2 + 1] = fmaf(ex2f(e3), cc.w, rowAcc[emf*2 + 1]);
        }
    }

    // quad reduction + cross-warpN reduction via smem
    #pragma unroll
    for (int i = 0; i < 4; ++i) {
        rowAcc[i] += __shfl_xor_sync(0xffffffffu, rowAcc[i], 1);
        rowAcc[i] += __shfl_xor_sync(0xffffffffu, rowAcc[i], 2);
    }
    __syncthreads();
    float* red = (float*)(smem + SM_RED);
    if (tq == 0) {
        #pragma unroll
        for (int mf = 0; mf < 2; ++mf)
            #pragma unroll
            for (int h8 = 0; h8 < 2; ++h8) {
                int row = warpM*32 + mf*16 + g + h8*8;
                red[row * 2 + warpN] = rowAcc[mf*2 + h8];
            }
    }
    __syncthreads();
    if (tid < 128) {
        int row = rowBase + tid;
        const int outLimit = isX ? nRows : mCols;
        if (row < outLimit) outp[row] = red[tid*2] + red[tid*2 + 1];
    }
}

// ===================== loss partials =====================
__global__ void sqerr_kernel(const float* __restrict__ preds, const float* __restrict__ Y,
                             float* __restrict__ partials, int n) {
    float s = 0.0f;
    for (int i = blockIdx.x * blockDim.x + threadIdx.x; i < n; i += gridDim.x * blockDim.x) {
        float d = preds[i] - Y[i];
        s = fmaf(d, d, s);
    }
    __shared__ float sm[256];
    sm[threadIdx.x] = s;
    __syncthreads();
    #pragma unroll
    for (int off = 128; off > 0; off >>= 1) {
        if (threadIdx.x < off) sm[threadIdx.x] += sm[threadIdx.x + off];
        __syncthreads();
    }
    if (threadIdx.x == 0) partials[blockIdx.x] = sm[0];
}

// ===================== finalize =====================
__global__ void final_kernel(const float* __restrict__ partials, int nPart,
                             const float* __restrict__ alpha,
                             const float* __restrict__ predsMM, int m,
                             const float* __restrict__ penalty_p,
                             float* __restrict__ out_total, int n) {
    int tid = threadIdx.x;
    float s = 0.0f;
    for (int i = tid; i < nPart; i += 256) s += partials[i];
    float rg = 0.0f;
    for (int i = tid; i < m; i += 256) rg = fmaf(alpha[i], predsMM[i], rg);
    __shared__ float sm[256], sm2[256];
    sm[tid] = s; sm2[tid] = rg;
    __syncthreads();
    #pragma unroll
    for (int off = 128; off > 0; off >>= 1) {
        if (tid < off) { sm[tid] += sm[tid + off]; sm2[tid] += sm2[tid + off]; }
        __syncthreads();
    }
    if (tid == 0)
        out_total[0] = sm[0] / (float)n + expf(-penalty_p[0]) * sm2[0];
}

// ===================== launch =====================
extern "C" void kernel_launch(void* const* d_in, const int* in_sizes, int n_in,
                              void* d_out, int out_size) {
    const float* X       = (const float*)d_in[0];
    const float* Y       = (const float*)d_in[1];
    const float* centers = (const float*)d_in[2];
    const float* alpha   = (const float*)d_in[3];
    const float* sigma   = (const float*)d_in[4];
    const float* penalty = (const float*)d_in[5];
    float* out = (float*)d_out;

    const int N = in_sizes[0] / DIMK;
    const int M = in_sizes[2] / DIMK;

    __nv_bfloat16* Cb;
    float *predsMM, *partials, *preds_fb;
    float2* c2a;
    cudaGetSymbolAddress((void**)&Cb,       g_Cb);
    cudaGetSymbolAddress((void**)&c2a,      g_c2a);
    cudaGetSymbolAddress((void**)&predsMM,  g_predsMM);
    cudaGetSymbolAddress((void**)&partials, g_partials);
    cudaGetSymbolAddress((void**)&preds_fb, g_preds_fallback);

    float* preds_ptr = preds_fb;
    float* total_ptr = out;
    if (out_size >= N + 1)  { total_ptr = out; preds_ptr = out + 1; }
    else if (out_size == N) { preds_ptr = out; total_ptr = preds_fb; }

    const int nBlocksX = (N + 127) / 128;
    const int nBlocksM = (M + 127) / 128;

    cudaFuncSetAttribute(rbf_hmma_kernel,
                         cudaFuncAttributeMaxDynamicSharedMemorySize, SMEM_TOTAL);

    convC_kernel<<<(M + 7) / 8, 256>>>(centers, Cb, c2a, alpha, sigma, M);

    rbf_hmma_kernel<<<nBlocksX + nBlocksM, 256, SMEM_TOTAL>>>(
        X, centers, Cb, c2a, sigma, preds_ptr, predsMM, N, nBlocksX, M);

    sqerr_kernel<<<256, 256>>>(preds_ptr, Y, partials, N);
    final_kernel<<<1, 256>>>(partials, 256, alpha, predsMM, M, penalty, total_ptr, N);
}

// round 6
// speedup vs baseline: 1.2669x; 1.2669x over previous
#include <cuda_runtime.h>
#include <cuda_bf16.h>
#include <cstdint>
#include <math.h>

// ===================== constants =====================
static constexpr int DIMK = 128;

// smem layout (bytes), dynamic
static constexpr int TS      = 272;                 // padded row stride (136 bf16)
static constexpr int TILE_B  = 128 * TS;            // 34816
static constexpr int SM_A    = 0;                   // A tile; overlaid by RED at end
static constexpr int SM_B0   = TILE_B;              // 34816
static constexpr int SM_B1   = 2 * TILE_B;          // 69632
static constexpr int SM_CA   = 3 * TILE_B;          // 104448, 2 slots x 1KB (float2[128])
static constexpr int SM_NORM = SM_CA + 2048;        // 106496, 128 floats
static constexpr int SMEM_TOTAL = SM_NORM + 1024;   // 107520

// ===================== scratch (no cudaMalloc) =====================
__device__ __nv_bfloat16 g_Cb[2048 * DIMK];
__device__ float2 g_c2a[2048];          // (-0.5*||c'||^2 , alpha)
__device__ float  g_predsMM[2048];
__device__ float  g_partials[512];
__device__ float  g_preds_fallback[100352];

// ===================== PTX helpers =====================
__device__ __forceinline__ uint32_t smem_u32(const void* p) {
    uint32_t a;
    asm("{ .reg .u64 t; cvta.to.shared.u64 t, %1; cvt.u32.u64 %0, t; }" : "=r"(a) : "l"(p));
    return a;
}
__device__ __forceinline__ void cpa16(uint32_t dst, const void* src) {
    asm volatile("cp.async.cg.shared.global [%0], [%1], 16;" :: "r"(dst), "l"(src));
}
#define CP_COMMIT() asm volatile("cp.async.commit_group;" ::: "memory")
#define CP_WAIT0()  asm volatile("cp.async.wait_group 0;"  ::: "memory")

__device__ __forceinline__ void ldmx4(uint32_t* r, uint32_t addr) {
    asm volatile("ldmatrix.sync.aligned.m8n8.x4.shared.b16 {%0,%1,%2,%3}, [%4];"
                 : "=r"(r[0]), "=r"(r[1]), "=r"(r[2]), "=r"(r[3]) : "r"(addr));
}
__device__ __forceinline__ void mma16816(float* c, const uint32_t* a,
                                         uint32_t b0, uint32_t b1) {
    asm volatile("mma.sync.aligned.m16n8k16.row.col.f32.bf16.bf16.f32 "
                 "{%0,%1,%2,%3}, {%4,%5,%6,%7}, {%8,%9}, {%0,%1,%2,%3};"
                 : "+f"(c[0]), "+f"(c[1]), "+f"(c[2]), "+f"(c[3])
                 : "r"(a[0]), "r"(a[1]), "r"(a[2]), "r"(a[3]), "r"(b0), "r"(b1));
}
__device__ __forceinline__ float ex2f(float x) {
    float y; asm("ex2.approx.ftz.f32 %0, %1;" : "=f"(y) : "f"(x)); return y;
}

// q = sqrt(log2e / sigma^2) so that (q a)·(q b) = 2*s2*a.b directly
__device__ __forceinline__ float qscale(float sg) {
    return sqrtf(1.44269504088896340736f) / sg;
}

// ===================== centers conv: fp32 -> bf16 (scaled), (d, alpha) ======
__global__ void convC_kernel(const float* __restrict__ C,
                             __nv_bfloat16* __restrict__ Cb,
                             float2* __restrict__ c2a,
                             const float* __restrict__ alpha,
                             const float* __restrict__ sigma_p, int m)
{
    int row  = blockIdx.x * 8 + (threadIdx.x >> 5);
    int lane = threadIdx.x & 31;
    if (row >= m) return;
    const float q = qscale(*sigma_p);
    float4 v = ((const float4*)(C + (size_t)row * DIMK))[lane];
    __nv_bfloat162 p0 = __floats2bfloat162_rn(q * v.x, q * v.y);
    __nv_bfloat162 p1 = __floats2bfloat162_rn(q * v.z, q * v.w);
    float r0 = __bfloat162float(p0.x), r1 = __bfloat162float(p0.y);
    float r2 = __bfloat162float(p1.x), r3 = __bfloat162float(p1.y);
    float s = r0*r0 + r1*r1 + r2*r2 + r3*r3;
    #pragma unroll
    for (int o = 16; o > 0; o >>= 1) s += __shfl_xor_sync(0xffffffffu, s, o);
    __nv_bfloat162* dst = (__nv_bfloat162*)(Cb + (size_t)row * DIMK) + lane * 2;
    dst[0] = p0; dst[1] = p1;
    if (lane == 0) c2a[row] = make_float2(-0.5f * s, alpha[row]);
}

// ===================== B-tile async loader (bf16 128x128, 128 threads) =====
__device__ __forceinline__ void load_tile_async(uint32_t smBase,
                                                const __nv_bfloat16* __restrict__ src,
                                                int tid)
{
    #pragma unroll
    for (int it = 0; it < 16; ++it) {
        int i   = tid + it * 128;
        int row = i >> 4;
        int kb  = i & 15;
        cpa16(smBase + row * TS + kb * 16, (const char*)src + row * 256 + kb * 16);
    }
}

// ===================== fused RBF matvec (HMMA, 4 fat warps) =================
// Blocks [0, nBlocksX): rows of X -> preds ; rest: rows of centers -> predsMM
__global__ void __launch_bounds__(128, 2)
rbf_hmma_kernel(const float* __restrict__ Xf, const float* __restrict__ Cf,
                const __nv_bfloat16* __restrict__ Cb,
                const float2* __restrict__ c2a,
                const float* __restrict__ sigma_p,
                float* __restrict__ preds, float* __restrict__ predsMM,
                int nRows, int nBlocksX, int mCols)
{
    extern __shared__ char smem[];
    const uint32_t sb = smem_u32(smem);
    const int tid   = threadIdx.x;
    const int lane  = tid & 31;
    const int wid   = tid >> 5;
    const int warpM = wid & 1;          // 2 warps over M (64 rows each)
    const int warpN = wid >> 1;         // 2 warps over N (64 cols each)
    const int g     = lane >> 2;
    const int tq    = lane & 3;

    const bool isX = ((int)blockIdx.x < nBlocksX);
    const float* Asrc  = isX ? Xf : Cf;
    const int   srcN   = isX ? nRows : mCols;
    float* outp        = isX ? preds : predsMM;
    const int rowBase  = (isX ? blockIdx.x : blockIdx.x - nBlocksX) * 128;

    const float q = qscale(*sigma_p);

    // ---- prologue: start async C tile 0 + CA slot 0 ----
    load_tile_async(sb + SM_B0, Cb, tid);
    if (tid < 64) cpa16(sb + SM_CA + tid * 16, (const char*)c2a + tid * 16);
    CP_COMMIT();

    // ---- load A tile fp32 -> scaled bf16 smem (coalesced) ----
    #pragma unroll
    for (int i = 0; i < 32; ++i) {
        int idx = tid + i * 128;            // 4096 float4 chunks
        int r = idx >> 5, c4 = idx & 31;
        int gr = rowBase + r; if (gr >= srcN) gr = srcN - 1;
        float4 v = ((const float4*)(Asrc + (size_t)gr * DIMK))[c4];
        __nv_bfloat162 p0 = __floats2bfloat162_rn(q * v.x, q * v.y);
        __nv_bfloat162 p1 = __floats2bfloat162_rn(q * v.z, q * v.w);
        uint2 w;
        w.x = *(const uint32_t*)&p0; w.y = *(const uint32_t*)&p1;
        *(uint2*)(smem + SM_A + r * TS + c4 * 8) = w;
    }
    CP_WAIT0();
    __syncthreads();

    // ---- row norms from ROUNDED scaled bf16 (1 thread/row) ----
    {
        float nrm = 0.f;
        #pragma unroll
        for (int j = 0; j < 16; ++j) {
            uint4 v = *(const uint4*)(smem + SM_A + tid * TS + j * 16);
            const uint32_t* u = (const uint32_t*)&v;
            #pragma unroll
            for (int qq = 0; qq < 4; ++qq) {
                float2 f = __bfloat1622float2(*(const __nv_bfloat162*)&u[qq]);
                nrm = fmaf(f.x, f.x, nrm);
                nrm = fmaf(f.y, f.y, nrm);
            }
        }
        ((float*)(smem + SM_NORM))[tid] = -0.5f * nrm;
    }
    __syncthreads();

    // caR[mf*2+h] = -0.5*||row||^2 for rows warpM*64 + mf*16 + g + h*8
    float caR[8];
    {
        const float* nm = (const float*)(smem + SM_NORM);
        #pragma unroll
        for (int mf = 0; mf < 4; ++mf)
            #pragma unroll
            for (int h = 0; h < 2; ++h)
                caR[mf*2 + h] = nm[warpM*64 + mf*16 + g + h*8];
    }

    // ldmatrix per-lane addressing
    const int ti = lane >> 3, rr = lane & 7;
    uint32_t aOff[4];   // A: 4 mf groups of 16 rows
    #pragma unroll
    for (int mf = 0; mf < 4; ++mf)
        aOff[mf] = (uint32_t)(SM_A + (warpM*64 + mf*16 + (ti & 1)*8 + rr) * TS
                              + (ti >> 1) * 16);
    uint32_t bOff[4];   // B: 4 groups of 16 cols
    #pragma unroll
    for (int p = 0; p < 4; ++p)
        bOff[p] = (uint32_t)((warpN*64 + p*16 + (ti >> 1)*8 + rr) * TS + (ti & 1) * 16);

    float acc[4][8][4];             // [mf][nf][e] = 128 accs
    float rowAcc[8] = {0.f,0.f,0.f,0.f,0.f,0.f,0.f,0.f};
    const int nT = mCols >> 7;      // 16

    for (int t = 0; t < nT; ++t) {
        if (t + 1 < nT) {
            load_tile_async(sb + (((t + 1) & 1) ? SM_B1 : SM_B0),
                            Cb + (size_t)(t + 1) * 128 * DIMK, tid);
            if (tid < 64)
                cpa16(sb + SM_CA + ((t + 1) & 1) * 1024 + tid * 16,
                      (const char*)(c2a + (size_t)(t + 1) * 128) + tid * 16);
            CP_COMMIT();
        }
        const uint32_t bB = sb + ((t & 1) ? SM_B1 : SM_B0);

        #pragma unroll
        for (int mf = 0; mf < 4; ++mf)
            #pragma unroll
            for (int nf = 0; nf < 8; ++nf)
                #pragma unroll
                for (int e = 0; e < 4; ++e) acc[mf][nf][e] = 0.f;

        #pragma unroll
        for (int ks = 0; ks < 8; ++ks) {
            const uint32_t kOff = ks * 32;
            uint32_t a[4][4];
            #pragma unroll
            for (int mf = 0; mf < 4; ++mf) ldmx4(a[mf], sb + aOff[mf] + kOff);
            uint32_t b[8][2];
            #pragma unroll
            for (int p = 0; p < 4; ++p) {
                uint32_t r4[4];
                ldmx4(r4, bB + bOff[p] + kOff);
                b[2*p][0]   = r4[0]; b[2*p][1]   = r4[1];
                b[2*p+1][0] = r4[2]; b[2*p+1][1] = r4[3];
            }
            #pragma unroll
            for (int mf = 0; mf < 4; ++mf)
                #pragma unroll
                for (int nf = 0; nf < 8; ++nf)
                    mma16816(acc[mf][nf], a[mf], b[nf][0], b[nf][1]);
        }

        // epilogue: w = exp2(f + caR + cc.x), rowAcc += w * alpha
        {
            const char* caP = smem + SM_CA + (t & 1) * 1024 + (size_t)warpN * 64 * 8;
            #pragma unroll
            for (int nf = 0; nf < 8; ++nf) {
                float4 cc = *(const float4*)(caP + (nf*8 + tq*2) * 8);
                #pragma unroll
                for (int mf = 0; mf < 4; ++mf) {
                    const float* a = acc[mf][nf];
                    float e0 = a[0] + (caR[mf*2]     + cc.x);
                    float e1 = a[1] + (caR[mf*2]     + cc.z);
                    float e2 = a[2] + (caR[mf*2 + 1] + cc.x);
                    float e3 = a[3] + (caR[mf*2 + 1] + cc.z);
                    rowAcc[mf*2]     = fmaf(ex2f(e0), cc.y, rowAcc[mf*2]);
                    rowAcc[mf*2]     = fmaf(ex2f(e1), cc.w, rowAcc[mf*2]);
                    rowAcc[mf*2 + 1] = fmaf(ex2f(e2), cc.y, rowAcc[mf*2 + 1]);
                    rowAcc[mf*2 + 1] = fmaf(ex2f(e3), cc.w, rowAcc[mf*2 + 1]);
                }
            }
        }

        CP_WAIT0();
        __syncthreads();
    }

    // quad reduce (4 threads share each row), then cross-warpN via smem
    #pragma unroll
    for (int i = 0; i < 8; ++i) {
        rowAcc[i] += __shfl_xor_sync(0xffffffffu, rowAcc[i], 1);
        rowAcc[i] += __shfl_xor_sync(0xffffffffu, rowAcc[i], 2);
    }
    __syncthreads();                       // A tile dead; overlay RED at SM_A
    float* red = (float*)(smem + SM_A);
    if (tq == 0) {
        #pragma unroll
        for (int mf = 0; mf < 4; ++mf)
            #pragma unroll
            for (int h = 0; h < 2; ++h) {
                int row = warpM*64 + mf*16 + g + h*8;
                red[row * 2 + warpN] = rowAcc[mf*2 + h];
            }
    }
    __syncthreads();
    {
        int row = rowBase + tid;
        const int outLimit = isX ? nRows : mCols;
        if (row < outLimit) outp[row] = red[tid*2] + red[tid*2 + 1];
    }
}

// ===================== loss partials =====================
__global__ void sqerr_kernel(const float* __restrict__ preds, const float* __restrict__ Y,
                             float* __restrict__ partials, int n) {
    float s = 0.0f;
    for (int i = blockIdx.x * blockDim.x + threadIdx.x; i < n; i += gridDim.x * blockDim.x) {
        float d = preds[i] - Y[i];
        s = fmaf(d, d, s);
    }
    __shared__ float sm[256];
    sm[threadIdx.x] = s;
    __syncthreads();
    #pragma unroll
    for (int off = 128; off > 0; off >>= 1) {
        if (threadIdx.x < off) sm[threadIdx.x] += sm[threadIdx.x + off];
        __syncthreads();
    }
    if (threadIdx.x == 0) partials[blockIdx.x] = sm[0];
}

// ===================== finalize =====================
__global__ void final_kernel(const float* __restrict__ partials, int nPart,
                             const float* __restrict__ alpha,
                             const float* __restrict__ predsMM, int m,
                             const float* __restrict__ penalty_p,
                             float* __restrict__ out_total, int n) {
    int tid = threadIdx.x;
    float s = 0.0f;
    for (int i = tid; i < nPart; i += 256) s += partials[i];
    float rg = 0.0f;
    for (int i = tid; i < m; i += 256) rg = fmaf(alpha[i], predsMM[i], rg);
    __shared__ float sm[256], sm2[256];
    sm[tid] = s; sm2[tid] = rg;
    __syncthreads();
    #pragma unroll
    for (int off = 128; off > 0; off >>= 1) {
        if (tid < off) { sm[tid] += sm[tid + off]; sm2[tid] += sm2[tid + off]; }
        __syncthreads();
    }
    if (tid == 0)
        out_total[0] = sm[0] / (float)n + expf(-penalty_p[0]) * sm2[0];
}

// ===================== launch =====================
extern "C" void kernel_launch(void* const* d_in, const int* in_sizes, int n_in,
                              void* d_out, int out_size) {
    const float* X       = (const float*)d_in[0];
    const float* Y       = (const float*)d_in[1];
    const float* centers = (const float*)d_in[2];
    const float* alpha   = (const float*)d_in[3];
    const float* sigma   = (const float*)d_in[4];
    const float* penalty = (const float*)d_in[5];
    float* out = (float*)d_out;

    const int N = in_sizes[0] / DIMK;
    const int M = in_sizes[2] / DIMK;

    __nv_bfloat16* Cb;
    float *predsMM, *partials, *preds_fb;
    float2* c2a;
    cudaGetSymbolAddress((void**)&Cb,       g_Cb);
    cudaGetSymbolAddress((void**)&c2a,      g_c2a);
    cudaGetSymbolAddress((void**)&predsMM,  g_predsMM);
    cudaGetSymbolAddress((void**)&partials, g_partials);
    cudaGetSymbolAddress((void**)&preds_fb, g_preds_fallback);

    float* preds_ptr = preds_fb;
    float* total_ptr = out;
    if (out_size >= N + 1)  { total_ptr = out; preds_ptr = out + 1; }
    else if (out_size == N) { preds_ptr = out; total_ptr = preds_fb; }

    const int nBlocksX = (N + 127) / 128;
    const int nBlocksM = (M + 127) / 128;

    cudaFuncSetAttribute(rbf_hmma_kernel,
                         cudaFuncAttributeMaxDynamicSharedMemorySize, SMEM_TOTAL);

    convC_kernel<<<(M + 7) / 8, 256>>>(centers, Cb, c2a, alpha, sigma, M);

    rbf_hmma_kernel<<<nBlocksX + nBlocksM, 128, SMEM_TOTAL>>>(
        X, centers, Cb, c2a, sigma, preds_ptr, predsMM, N, nBlocksX, M);

    sqerr_kernel<<<256, 256>>>(preds_ptr, Y, partials, N);
    final_kernel<<<1, 256>>>(partials, 256, alpha, predsMM, M, penalty, total_ptr, N);
}

// round 7
// speedup vs baseline: 1.2837x; 1.0133x over previous
#include <cuda_runtime.h>
#include <cuda_bf16.h>
#include <cstdint>
#include <math.h>

// ===================== constants =====================
static constexpr int DIMK = 128;

// smem layout (bytes), dynamic
static constexpr int TS      = 272;                 // padded row stride (136 bf16)
static constexpr int TILE_B  = 128 * TS;            // 34816
static constexpr int SM_A    = 0;                   // A tile; overlaid by RED at end
static constexpr int SM_B0   = TILE_B;              // 34816
static constexpr int SM_B1   = 2 * TILE_B;          // 69632
static constexpr int SM_CA   = 3 * TILE_B;          // 104448, 2 slots x 1KB (float2[128])
static constexpr int SM_NORM = SM_CA + 2048;        // 106496, 128 floats
static constexpr int SMEM_TOTAL = SM_NORM + 1024;   // 107520

// ===================== scratch (no cudaMalloc) =====================
__device__ __nv_bfloat16 g_Cb[2048 * DIMK];
__device__ float2 g_c2a[2048];          // (-0.5*||c'||^2 , alpha)
__device__ float  g_predsMM[2048];
__device__ float  g_partials[1024];     // per-block loss/reg partials
__device__ float  g_preds_fallback[100352];

// ===================== PTX helpers =====================
__device__ __forceinline__ uint32_t smem_u32(const void* p) {
    uint32_t a;
    asm("{ .reg .u64 t; cvta.to.shared.u64 t, %1; cvt.u32.u64 %0, t; }" : "=r"(a) : "l"(p));
    return a;
}
__device__ __forceinline__ void cpa16(uint32_t dst, const void* src) {
    asm volatile("cp.async.cg.shared.global [%0], [%1], 16;" :: "r"(dst), "l"(src));
}
#define CP_COMMIT() asm volatile("cp.async.commit_group;" ::: "memory")
#define CP_WAIT0()  asm volatile("cp.async.wait_group 0;"  ::: "memory")

__device__ __forceinline__ void ldmx4(uint32_t* r, uint32_t addr) {
    asm volatile("ldmatrix.sync.aligned.m8n8.x4.shared.b16 {%0,%1,%2,%3}, [%4];"
                 : "=r"(r[0]), "=r"(r[1]), "=r"(r[2]), "=r"(r[3]) : "r"(addr));
}
__device__ __forceinline__ void mma16816(float* c, const uint32_t* a,
                                         uint32_t b0, uint32_t b1) {
    asm volatile("mma.sync.aligned.m16n8k16.row.col.f32.bf16.bf16.f32 "
                 "{%0,%1,%2,%3}, {%4,%5,%6,%7}, {%8,%9}, {%0,%1,%2,%3};"
                 : "+f"(c[0]), "+f"(c[1]), "+f"(c[2]), "+f"(c[3])
                 : "r"(a[0]), "r"(a[1]), "r"(a[2]), "r"(a[3]), "r"(b0), "r"(b1));
}
__device__ __forceinline__ float ex2f(float x) {
    float y; asm("ex2.approx.ftz.f32 %0, %1;" : "=f"(y) : "f"(x)); return y;
}
// q = sqrt(log2e)/sigma so that (q a)·(q b) = log2e * (a.b)/sigma^2
__device__ __forceinline__ float qscale(float sg) {
    return sqrtf(1.44269504088896340736f) / sg;
}

// ===================== centers conv: fp32 -> bf16 (scaled), (d, alpha) ======
__global__ void convC_kernel(const float* __restrict__ C,
                             __nv_bfloat16* __restrict__ Cb,
                             float2* __restrict__ c2a,
                             const float* __restrict__ alpha,
                             const float* __restrict__ sigma_p, int m)
{
    int row  = blockIdx.x * 8 + (threadIdx.x >> 5);
    int lane = threadIdx.x & 31;
    if (row >= m) return;
    const float q = qscale(*sigma_p);
    float4 v = ((const float4*)(C + (size_t)row * DIMK))[lane];
    __nv_bfloat162 p0 = __floats2bfloat162_rn(q * v.x, q * v.y);
    __nv_bfloat162 p1 = __floats2bfloat162_rn(q * v.z, q * v.w);
    float r0 = __bfloat162float(p0.x), r1 = __bfloat162float(p0.y);
    float r2 = __bfloat162float(p1.x), r3 = __bfloat162float(p1.y);
    float s = r0*r0 + r1*r1 + r2*r2 + r3*r3;
    #pragma unroll
    for (int o = 16; o > 0; o >>= 1) s += __shfl_xor_sync(0xffffffffu, s, o);
    __nv_bfloat162* dst = (__nv_bfloat162*)(Cb + (size_t)row * DIMK) + lane * 2;
    dst[0] = p0; dst[1] = p1;
    if (lane == 0) c2a[row] = make_float2(-0.5f * s, alpha[row]);
}

// ===================== B-tile async loader (bf16 128x128, 128 threads) =====
__device__ __forceinline__ void load_tile_async(uint32_t smBase,
                                                const __nv_bfloat16* __restrict__ src,
                                                int tid)
{
    #pragma unroll
    for (int it = 0; it < 16; ++it) {
        int i   = tid + it * 128;
        int row = i >> 4;
        int kb  = i & 15;
        cpa16(smBase + row * TS + kb * 16, (const char*)src + row * 256 + kb * 16);
    }
}

// ===================== fused RBF matvec + loss partials =====================
// Blocks [0, nBlocksX): rows of X -> preds, partial = sum (pred-y)^2
// rest: rows of centers -> predsMM,  partial = sum alpha*predMM
__global__ void __launch_bounds__(128, 2)
rbf_hmma_kernel(const float* __restrict__ Xf, const float* __restrict__ Cf,
                const __nv_bfloat16* __restrict__ Cb,
                const float2* __restrict__ c2a,
                const float* __restrict__ Y,
                const float* __restrict__ sigma_p,
                float* __restrict__ preds, float* __restrict__ predsMM,
                float* __restrict__ partials,
                int nRows, int nBlocksX, int mCols)
{
    extern __shared__ char smem[];
    const uint32_t sb = smem_u32(smem);
    const int tid   = threadIdx.x;
    const int lane  = tid & 31;
    const int wid   = tid >> 5;
    const int warpM = wid & 1;          // 2 warps over M (64 rows each)
    const int warpN = wid >> 1;         // 2 warps over N (64 cols each)
    const int g     = lane >> 2;
    const int tq    = lane & 3;

    const bool isX = ((int)blockIdx.x < nBlocksX);
    const float* Asrc  = isX ? Xf : Cf;
    const int   srcN   = isX ? nRows : mCols;
    float* outp        = isX ? preds : predsMM;
    const int rowBase  = (isX ? blockIdx.x : blockIdx.x - nBlocksX) * 128;

    const float q = qscale(*sigma_p);

    // ---- prologue: start async C tile 0 + CA slot 0 ----
    load_tile_async(sb + SM_B0, Cb, tid);
    if (tid < 64) cpa16(sb + SM_CA + tid * 16, (const char*)c2a + tid * 16);
    CP_COMMIT();

    // ---- load A tile fp32 -> scaled bf16 smem (coalesced) ----
    #pragma unroll
    for (int i = 0; i < 32; ++i) {
        int idx = tid + i * 128;            // 4096 float4 chunks
        int r = idx >> 5, c4 = idx & 31;
        int gr = rowBase + r; if (gr >= srcN) gr = srcN - 1;
        float4 v = ((const float4*)(Asrc + (size_t)gr * DIMK))[c4];
        __nv_bfloat162 p0 = __floats2bfloat162_rn(q * v.x, q * v.y);
        __nv_bfloat162 p1 = __floats2bfloat162_rn(q * v.z, q * v.w);
        uint2 w;
        w.x = *(const uint32_t*)&p0; w.y = *(const uint32_t*)&p1;
        *(uint2*)(smem + SM_A + r * TS + c4 * 8) = w;
    }
    __syncthreads();

    // ---- row norms from ROUNDED scaled bf16 (1 thread/row) ----
    {
        float nrm = 0.f;
        #pragma unroll
        for (int j = 0; j < 16; ++j) {
            uint4 v = *(const uint4*)(smem + SM_A + tid * TS + j * 16);
            const uint32_t* u = (const uint32_t*)&v;
            #pragma unroll
            for (int qq = 0; qq < 4; ++qq) {
                float2 f = __bfloat1622float2(*(const __nv_bfloat162*)&u[qq]);
                nrm = fmaf(f.x, f.x, nrm);
                nrm = fmaf(f.y, f.y, nrm);
            }
        }
        ((float*)(smem + SM_NORM))[tid] = -0.5f * nrm;
    }
    __syncthreads();

    // caR[mf*2+h] = -0.5*||row||^2 for rows warpM*64 + mf*16 + g + h*8
    float caR[8];
    {
        const float* nm = (const float*)(smem + SM_NORM);
        #pragma unroll
        for (int mf = 0; mf < 4; ++mf)
            #pragma unroll
            for (int h = 0; h < 2; ++h)
                caR[mf*2 + h] = nm[warpM*64 + mf*16 + g + h*8];
    }

    // ---- A fragments persist in registers across ALL tiles ----
    const int ti = lane >> 3, rr = lane & 7;
    uint32_t aF[4][8][4];               // [mf][ks][4] = 128 regs
    #pragma unroll
    for (int mf = 0; mf < 4; ++mf) {
        uint32_t base = sb + SM_A + (warpM*64 + mf*16 + (ti & 1)*8 + rr) * TS
                        + (ti >> 1) * 16;
        #pragma unroll
        for (int ks = 0; ks < 8; ++ks) ldmx4(aF[mf][ks], base + ks * 32);
    }

    // B ldmatrix offsets (4 slices of 16 cols)
    uint32_t bOff[4];
    #pragma unroll
    for (int p = 0; p < 4; ++p)
        bOff[p] = (uint32_t)((warpN*64 + p*16 + (ti >> 1)*8 + rr) * TS + (ti & 1) * 16);

    float rowAcc[8] = {0.f,0.f,0.f,0.f,0.f,0.f,0.f,0.f};
    const int nT = mCols >> 7;      // 16
    CP_WAIT0();
    __syncthreads();

    for (int t = 0; t < nT; ++t) {
        if (t + 1 < nT) {
            load_tile_async(sb + (((t + 1) & 1) ? SM_B1 : SM_B0),
                            Cb + (size_t)(t + 1) * 128 * DIMK, tid);
            if (tid < 64)
                cpa16(sb + SM_CA + ((t + 1) & 1) * 1024 + tid * 16,
                      (const char*)(c2a + (size_t)(t + 1) * 128) + tid * 16);
            CP_COMMIT();
        }
        const uint32_t bB  = sb + ((t & 1) ? SM_B1 : SM_B0);
        const char*   caP  = smem + SM_CA + (t & 1) * 1024 + (size_t)warpN * 64 * 8;

        // 4 slices of 16 cols: short MMA burst + immediate epilogue (pipe mixing)
        #pragma unroll
        for (int p = 0; p < 4; ++p) {
            float acc[4][2][4];
            #pragma unroll
            for (int mf = 0; mf < 4; ++mf)
                #pragma unroll
                for (int nl = 0; nl < 2; ++nl)
                    #pragma unroll
                    for (int e = 0; e < 4; ++e) acc[mf][nl][e] = 0.f;

            uint32_t rb[2][4];
            ldmx4(rb[0], bB + bOff[p]);
            #pragma unroll
            for (int ks = 0; ks < 8; ++ks) {
                if (ks < 7) ldmx4(rb[(ks + 1) & 1], bB + bOff[p] + (ks + 1) * 32);
                const uint32_t* b = rb[ks & 1];
                #pragma unroll
                for (int mf = 0; mf < 4; ++mf) {
                    mma16816(acc[mf][0], aF[mf][ks], b[0], b[1]);
                    mma16816(acc[mf][1], aF[mf][ks], b[2], b[3]);
                }
            }
            // epilogue for this 16-col slice
            #pragma unroll
            for (int nl = 0; nl < 2; ++nl) {
                float4 cc = *(const float4*)(caP + ((p*2 + nl)*8 + tq*2) * 8);
                #pragma unroll
                for (int mf = 0; mf < 4; ++mf) {
                    const float* a = acc[mf][nl];
                    float e0 = a[0] + (caR[mf*2]     + cc.x);
                    float e1 = a[1] + (caR[mf*2]     + cc.z);
                    float e2 = a[2] + (caR[mf*2 + 1] + cc.x);
                    float e3 = a[3] + (caR[mf*2 + 1] + cc.z);
                    rowAcc[mf*2]     = fmaf(ex2f(e0), cc.y, rowAcc[mf*2]);
                    rowAcc[mf*2]     = fmaf(ex2f(e1), cc.w, rowAcc[mf*2]);
                    rowAcc[mf*2 + 1] = fmaf(ex2f(e2), cc.y, rowAcc[mf*2 + 1]);
                    rowAcc[mf*2 + 1] = fmaf(ex2f(e3), cc.w, rowAcc[mf*2 + 1]);
                }
            }
        }
        CP_WAIT0();
        __syncthreads();
    }

    // quad reduce (4 threads share each row), then cross-warpN via smem
    #pragma unroll
    for (int i = 0; i < 8; ++i) {
        rowAcc[i] += __shfl_xor_sync(0xffffffffu, rowAcc[i], 1);
        rowAcc[i] += __shfl_xor_sync(0xffffffffu, rowAcc[i], 2);
    }
    __syncthreads();                       // tiles dead; overlay RED at SM_A
    float* red = (float*)(smem + SM_A);
    if (tq == 0) {
        #pragma unroll
        for (int mf = 0; mf < 4; ++mf)
            #pragma unroll
            for (int h = 0; h < 2; ++h) {
                int row = warpM*64 + mf*16 + g + h*8;
                red[row * 2 + warpN] = rowAcc[mf*2 + h];
            }
    }
    __syncthreads();

    // final value per row + fused loss partial
    {
        int row = rowBase + tid;
        const int outLimit = isX ? nRows : mCols;
        float val = red[tid*2] + red[tid*2 + 1];
        float contrib = 0.f;
        if (row < outLimit) {
            outp[row] = val;
            if (isX) {
                float d = val - Y[row];
                contrib = d * d;
            } else {
                contrib = c2a[row].y * val;    // alpha * predMM
            }
        }
        // block reduction of 128 contribs (fixed order)
        __syncthreads();
        float* blk = (float*)(smem + SM_A);
        blk[tid] = contrib;
        __syncthreads();
        #pragma unroll
        for (int off = 64; off > 0; off >>= 1) {
            if (tid < off) blk[tid] += blk[tid + off];
            __syncthreads();
        }
        if (tid == 0) partials[blockIdx.x] = blk[0];
    }
}

// ===================== finalize =====================
__global__ void final_kernel(const float* __restrict__ partials,
                             int nBlocksX, int nBlocksTot,
                             const float* __restrict__ penalty_p,
                             float* __restrict__ out_total, int n) {
    int tid = threadIdx.x;
    float s = 0.0f, rg = 0.0f;
    for (int i = tid; i < nBlocksX; i += 256) s += partials[i];
    for (int i = nBlocksX + tid; i < nBlocksTot; i += 256) rg += partials[i];
    __shared__ float sm[256], sm2[256];
    sm[tid] = s; sm2[tid] = rg;
    __syncthreads();
    #pragma unroll
    for (int off = 128; off > 0; off >>= 1) {
        if (tid < off) { sm[tid] += sm[tid + off]; sm2[tid] += sm2[tid + off]; }
        __syncthreads();
    }
    if (tid == 0)
        out_total[0] = sm[0] / (float)n + expf(-penalty_p[0]) * sm2[0];
}

// ===================== launch =====================
extern "C" void kernel_launch(void* const* d_in, const int* in_sizes, int n_in,
                              void* d_out, int out_size) {
    const float* X       = (const float*)d_in[0];
    const float* Y       = (const float*)d_in[1];
    const float* centers = (const float*)d_in[2];
    const float* alpha   = (const float*)d_in[3];
    const float* sigma   = (const float*)d_in[4];
    const float* penalty = (const float*)d_in[5];
    float* out = (float*)d_out;

    const int N = in_sizes[0] / DIMK;
    const int M = in_sizes[2] / DIMK;

    __nv_bfloat16* Cb;
    float *predsMM, *partials, *preds_fb;
    float2* c2a;
    cudaGetSymbolAddress((void**)&Cb,       g_Cb);
    cudaGetSymbolAddress((void**)&c2a,      g_c2a);
    cudaGetSymbolAddress((void**)&predsMM,  g_predsMM);
    cudaGetSymbolAddress((void**)&partials, g_partials);
    cudaGetSymbolAddress((void**)&preds_fb, g_preds_fallback);

    float* preds_ptr = preds_fb;
    float* total_ptr = out;
    if (out_size >= N + 1)  { total_ptr = out; preds_ptr = out + 1; }
    else if (out_size == N) { preds_ptr = out; total_ptr = preds_fb; }

    const int nBlocksX = (N + 127) / 128;
    const int nBlocksM = (M + 127) / 128;
    const int nBlocksTot = nBlocksX + nBlocksM;

    cudaFuncSetAttribute(rbf_hmma_kernel,
                         cudaFuncAttributeMaxDynamicSharedMemorySize, SMEM_TOTAL);

    convC_kernel<<<(M + 7) / 8, 256>>>(centers, Cb, c2a, alpha, sigma, M);

    rbf_hmma_kernel<<<nBlocksTot, 128, SMEM_TOTAL>>>(
        X, centers, Cb, c2a, Y, sigma, preds_ptr, predsMM, partials,
        N, nBlocksX, M);

    final_kernel<<<1, 256>>>(partials, nBlocksX, nBlocksTot, penalty, total_ptr, N);
}